// round 11
// baseline (speedup 1.0000x reference)
#include <cuda_runtime.h>
#include <math.h>
#include <stdint.h>

// Problem constants
#define NQ 512
#define NC 65536
#define D  768
#define PD 64          // packed projection dim: e[0:32) h[32:48) s[48:64)

typedef unsigned long long u64;

// packed-fp32 helpers (sm_103 f32x2 — 2x FFMA throughput, exact fp32)
__device__ __forceinline__ u64 pack2(float v) {
    u64 r;
    asm("mov.b64 %0, {%1, %1};" : "=l"(r) : "f"(v));
    return r;
}
__device__ __forceinline__ void fma2(u64& d, u64 a, u64 b) {
    asm("fma.rn.f32x2 %0, %1, %2, %0;" : "+l"(d) : "l"(a), "l"(b));
}
__device__ __forceinline__ void unpack2(float& lo, float& hi, u64 v) {
    asm("mov.b64 {%0, %1}, %2;" : "=f"(lo), "=f"(hi) : "l"(v));
}

// Scratch (no allocations allowed)
__device__ float g_c[(size_t)NC * PD];   // corpus projections [row][64]
__device__ float g_cyn[NC];              // tanh^2(||h_lin||)
__device__ float g_q[(size_t)NQ * PD];
__device__ float g_qxn[NQ];
__device__ float g_qw[(size_t)NQ * 3];

// ---------------------------------------------------------------------------
// Kernel 1: weight MLP (unchanged from R5-passing version)
// ---------------------------------------------------------------------------
__global__ __launch_bounds__(256) void mlp_kernel(
    const float* __restrict__ xq,
    const float* __restrict__ W1, const float* __restrict__ b1,
    const float* __restrict__ W2, const float* __restrict__ b2)
{
    __shared__ float xs[D];
    __shared__ float hid[32];

    const int q    = blockIdx.x;
    const int tid  = threadIdx.x;
    const int warp = tid >> 5, lane = tid & 31;

    const float4* xrow4 = (const float4*)(xq + (size_t)q * D);
    if (tid < D / 4) ((float4*)xs)[tid] = xrow4[tid];
    __syncthreads();

    float acc0 = 0.f, acc1 = 0.f, acc2 = 0.f, acc3 = 0.f;
    const float* w0  = W1 + (size_t)(warp * 4 + 0) * D;
    const float* w1r = W1 + (size_t)(warp * 4 + 1) * D;
    const float* w2r = W1 + (size_t)(warp * 4 + 2) * D;
    const float* w3r = W1 + (size_t)(warp * 4 + 3) * D;
    #pragma unroll 4
    for (int k = lane; k < D; k += 32) {
        float xv = xs[k];
        acc0 = fmaf(w0[k],  xv, acc0);
        acc1 = fmaf(w1r[k], xv, acc1);
        acc2 = fmaf(w2r[k], xv, acc2);
        acc3 = fmaf(w3r[k], xv, acc3);
    }
    #pragma unroll
    for (int o = 16; o; o >>= 1) {
        acc0 += __shfl_xor_sync(0xffffffffu, acc0, o);
        acc1 += __shfl_xor_sync(0xffffffffu, acc1, o);
        acc2 += __shfl_xor_sync(0xffffffffu, acc2, o);
        acc3 += __shfl_xor_sync(0xffffffffu, acc3, o);
    }
    if (lane == 0) {
        hid[warp * 4 + 0] = fmaxf(acc0 + b1[warp * 4 + 0], 0.0f);
        hid[warp * 4 + 1] = fmaxf(acc1 + b1[warp * 4 + 1], 0.0f);
        hid[warp * 4 + 2] = fmaxf(acc2 + b1[warp * 4 + 2], 0.0f);
        hid[warp * 4 + 3] = fmaxf(acc3 + b1[warp * 4 + 3], 0.0f);
    }
    __syncthreads();

    if (warp == 0) {
        float h = hid[lane];
        #pragma unroll
        for (int i = 0; i < 3; i++) {
            float p = h * W2[i * 32 + lane];
            #pragma unroll
            for (int o = 16; o; o >>= 1) p += __shfl_xor_sync(0xffffffffu, p, o);
            if (lane == 0) {
                float z  = p + b2[i];
                float sp = fmaxf(z, 0.0f) + log1pf(expf(-fabsf(z)));
                g_qw[(size_t)q * 3 + i] = sp;
            }
        }
    }
}

// ---------------------------------------------------------------------------
// Kernel 2: projection GEMM [rows,768]x[768,64] + fused epilogue.
// M=128 rows/block, 256 threads, 8x4 thread tile (f32x2), BK=32.
// Output staging overlaps the mainloop tiles (union region).
// ---------------------------------------------------------------------------
#define BK 32
#define ROWPAD 132        // rows dim pad: conflict-free transposed stores
#define NCB128 (NC / 128) // 512 corpus blocks
#define NQB128 (NQ / 128) // 4 query blocks

#define XS_OFF  0                         // xs[BK][ROWPAD] floats
#define WS_OFF  (BK * ROWPAD)             // wsm[BK][68] floats
#define OB_SZ   (128 * 68)                // ob[128][68] floats (overlaps xs/wsm)
#define SRAW_FLOATS (OB_SZ > (BK*ROWPAD + BK*68) ? OB_SZ : (BK*ROWPAD + BK*68))

__global__ __launch_bounds__(256) void proj_kernel(
    const float* __restrict__ xc,
    const float* __restrict__ xq,
    const float* __restrict__ We, const float* __restrict__ be,
    const float* __restrict__ Wh, const float* __restrict__ bh,
    const float* __restrict__ Ws, const float* __restrict__ bs,
    const float* __restrict__ scale_h_p)
{
    __shared__ __align__(16) float sraw[SRAW_FLOATS];
    __shared__ float bias_s[64];

    float* xs  = sraw + XS_OFF;   // xs[k][row]  row-pitch ROWPAD
    float* wsm = sraw + WS_OFF;   // wsm[k][col] col-pitch 68
    float* ob  = sraw;            // ob[row][col] pitch 68 (after mainloop)

    const int tid = threadIdx.x;
    const int blk = blockIdx.x;
    const bool isQ  = (blk >= NCB128);
    const int  row0 = isQ ? (blk - NCB128) * 128 : blk * 128;
    const float* xsrc = isQ ? xq : xc;
    float* gout = isQ ? g_q  : g_c;
    float* gyn  = isQ ? g_qxn : g_cyn;

    if (tid < 64) {
        float b;
        if (tid < 32)      b = be[tid];
        else if (tid < 48) b = bh[tid - 32];
        else               b = bs[tid - 48];
        bias_s[tid] = b;
    }

    // loading roles: x -> 4 float4/thread, w -> 2 float4/thread per chunk
    // idx layout: row = idx>>3, k4 = (idx&7)*4
    const float* wrow_base[2];
    {
        int n0 = (tid + 0 * 256) >> 3;     // 0..63 over the 512 w-float4s
        int n1 = (tid + 1 * 256) >> 3;
        wrow_base[0] = (n0 < 32) ? We + (size_t)n0 * D
                      : (n0 < 48) ? Wh + (size_t)(n0 - 32) * D
                                  : Ws + (size_t)(n0 - 48) * D;
        wrow_base[1] = (n1 < 32) ? We + (size_t)n1 * D
                      : (n1 < 48) ? Wh + (size_t)(n1 - 32) * D
                                  : Ws + (size_t)(n1 - 48) * D;
    }

    // compute roles: 8 rows x 4 cols per thread
    const int tr = (tid >> 4) * 8;    // 0..120
    const int tc = (tid & 15) * 4;    // 0..60

    u64 acc[8][2] = {};
    const float* xbase = xsrc + (size_t)row0 * D;

    for (int kk = 0; kk < D; kk += BK) {
        // stage loads into registers
        float4 xv[4], wv[2];
        #pragma unroll
        for (int i = 0; i < 4; i++) {
            int idx = tid + i * 256;            // 0..1023
            int r   = idx >> 3;                 // 0..127
            int k4  = (idx & 7) * 4;            // 0..28
            xv[i] = *(const float4*)(xbase + (size_t)r * D + kk + k4);
        }
        #pragma unroll
        for (int i = 0; i < 2; i++) {
            int idx = tid + i * 256;            // 0..511
            int k4  = (idx & 7) * 4;
            wv[i] = *(const float4*)(wrow_base[i] + kk + k4);
        }
        __syncthreads();
        #pragma unroll
        for (int i = 0; i < 4; i++) {
            int idx = tid + i * 256;
            int r   = idx >> 3;
            int k4  = (idx & 7) * 4;
            xs[(k4 + 0) * ROWPAD + r] = xv[i].x;
            xs[(k4 + 1) * ROWPAD + r] = xv[i].y;
            xs[(k4 + 2) * ROWPAD + r] = xv[i].z;
            xs[(k4 + 3) * ROWPAD + r] = xv[i].w;
        }
        #pragma unroll
        for (int i = 0; i < 2; i++) {
            int idx = tid + i * 256;
            int n   = idx >> 3;
            int k4  = (idx & 7) * 4;
            wsm[(k4 + 0) * 68 + n] = wv[i].x;
            wsm[(k4 + 1) * 68 + n] = wv[i].y;
            wsm[(k4 + 2) * 68 + n] = wv[i].z;
            wsm[(k4 + 3) * 68 + n] = wv[i].w;
        }
        __syncthreads();

        #pragma unroll
        for (int k = 0; k < BK; k++) {
            float4 a0 = *(const float4*)&xs[k * ROWPAD + tr];
            float4 a1 = *(const float4*)&xs[k * ROWPAD + tr + 4];
            ulonglong2 b = *(const ulonglong2*)&wsm[k * 68 + tc];
            u64 ap[8];
            ap[0] = pack2(a0.x); ap[1] = pack2(a0.y);
            ap[2] = pack2(a0.z); ap[3] = pack2(a0.w);
            ap[4] = pack2(a1.x); ap[5] = pack2(a1.y);
            ap[6] = pack2(a1.z); ap[7] = pack2(a1.w);
            #pragma unroll
            for (int i = 0; i < 8; i++) {
                fma2(acc[i][0], ap[i], b.x);
                fma2(acc[i][1], ap[i], b.y);
            }
        }
        __syncthreads();   // protect xs/wsm before next chunk's stores
    }

    // stage accumulators into ob (overlaps xs/wsm — mainloop reads done)
    #pragma unroll
    for (int i = 0; i < 8; i++) {
        float v0, v1, v2, v3;
        unpack2(v0, v1, acc[i][0]);
        unpack2(v2, v3, acc[i][1]);
        float4 w4 = {v0, v1, v2, v3};
        *(float4*)&ob[(tr + i) * 68 + tc] = w4;
    }
    __syncthreads();

    // epilogue: 128 rows x 4 parts = 512 tasks, 2 iterations.
    // part 0,1 -> e (32 cols, shuffle-combined), part 2 -> h, part 3 -> s
    const float sc = *scale_h_p;
    #pragma unroll
    for (int it = 0; it < 2; it++) {
        const int r    = (tid >> 2) + it * 64;
        const int part = tid & 3;
        const int cbase = part * 16;
        float vals[16];
        float ss = 0.0f;
        #pragma unroll
        for (int j = 0; j < 16; j++) {
            float v = ob[r * 68 + cbase + j] + bias_s[cbase + j];
            if (part == 2) v *= sc;
            vals[j] = v;
            ss += v * v;
        }
        float other = __shfl_xor_sync(0xffffffffu, ss, 1);
        float seg   = (part < 2) ? (ss + other) : ss;

        const int grow = row0 + r;
        float* orow = gout + (size_t)grow * PD + cbase;
        if (part == 2) {
            float n  = fmaxf(sqrtf(seg), 1e-15f);
            // tanh(n) = 1 - 2/(exp(2n)+1)  (n >= 0)
            float ex = __expf(2.0f * n);
            float th = 1.0f - 2.0f / (ex + 1.0f);
            float f  = th / n;
            #pragma unroll
            for (int j = 0; j < 16; j++) orow[j] = vals[j] * f;
            gyn[grow] = th * th;
        } else {
            float inv = rsqrtf(seg);
            #pragma unroll
            for (int j = 0; j < 16; j++) orow[j] = vals[j] * inv;
        }
    }
}

// ---------------------------------------------------------------------------
// Kernel 3: pairwise distances + weighted combine (unchanged from R5).
// ---------------------------------------------------------------------------
__global__ __launch_bounds__(256) void pairwise_kernel(float* __restrict__ out)
{
    __shared__ __align__(16) float qs[64][68];
    __shared__ __align__(16) float cs[64][68];
    __shared__ float sqxn[64];
    __shared__ float sqw[64][3];
    __shared__ float scyn[64];

    const int tid   = threadIdx.x;
    const int c0blk = blockIdx.x * 64;
    const int q0blk = blockIdx.y * 64;

    #pragma unroll
    for (int i = 0; i < 4; i++) {
        int f4  = tid + i * 256;
        int row = f4 >> 4;
        int k4  = (f4 & 15) * 4;
        float4 v = *(const float4*)(g_q + (size_t)(q0blk + row) * PD + k4);
        qs[k4+0][row] = v.x; qs[k4+1][row] = v.y;
        qs[k4+2][row] = v.z; qs[k4+3][row] = v.w;
        float4 w = *(const float4*)(g_c + (size_t)(c0blk + row) * PD + k4);
        cs[k4+0][row] = w.x; cs[k4+1][row] = w.y;
        cs[k4+2][row] = w.z; cs[k4+3][row] = w.w;
    }
    if (tid < 64) {
        sqxn[tid]   = g_qxn[q0blk + tid];
        scyn[tid]   = g_cyn[c0blk + tid];
        sqw[tid][0] = g_qw[(size_t)(q0blk + tid) * 3 + 0];
        sqw[tid][1] = g_qw[(size_t)(q0blk + tid) * 3 + 1];
        sqw[tid][2] = g_qw[(size_t)(q0blk + tid) * 3 + 2];
    }
    __syncthreads();

    const int tq0 = (tid >> 4) * 4;
    const int tc0 = (tid & 15) * 4;

    u64 ae[4][2] = {}, ah[4][2] = {}, as2[4][2] = {};

    #pragma unroll
    for (int k = 0; k < 32; k++) {
        float4 a = *(const float4*)&qs[k][tq0];
        ulonglong2 b = *(const ulonglong2*)&cs[k][tc0];
        u64 ap0 = pack2(a.x), ap1 = pack2(a.y),
            ap2 = pack2(a.z), ap3 = pack2(a.w);
        fma2(ae[0][0], ap0, b.x); fma2(ae[0][1], ap0, b.y);
        fma2(ae[1][0], ap1, b.x); fma2(ae[1][1], ap1, b.y);
        fma2(ae[2][0], ap2, b.x); fma2(ae[2][1], ap2, b.y);
        fma2(ae[3][0], ap3, b.x); fma2(ae[3][1], ap3, b.y);
    }
    #pragma unroll
    for (int k = 32; k < 48; k++) {
        float4 a = *(const float4*)&qs[k][tq0];
        ulonglong2 b = *(const ulonglong2*)&cs[k][tc0];
        u64 ap0 = pack2(a.x), ap1 = pack2(a.y),
            ap2 = pack2(a.z), ap3 = pack2(a.w);
        fma2(ah[0][0], ap0, b.x); fma2(ah[0][1], ap0, b.y);
        fma2(ah[1][0], ap1, b.x); fma2(ah[1][1], ap1, b.y);
        fma2(ah[2][0], ap2, b.x); fma2(ah[2][1], ap2, b.y);
        fma2(ah[3][0], ap3, b.x); fma2(ah[3][1], ap3, b.y);
    }
    #pragma unroll
    for (int k = 48; k < 64; k++) {
        float4 a = *(const float4*)&qs[k][tq0];
        ulonglong2 b = *(const ulonglong2*)&cs[k][tc0];
        u64 ap0 = pack2(a.x), ap1 = pack2(a.y),
            ap2 = pack2(a.z), ap3 = pack2(a.w);
        fma2(as2[0][0], ap0, b.x); fma2(as2[0][1], ap0, b.y);
        fma2(as2[1][0], ap1, b.x); fma2(as2[1][1], ap1, b.y);
        fma2(as2[2][0], ap2, b.x); fma2(as2[2][1], ap2, b.y);
        fma2(as2[3][0], ap3, b.x); fma2(as2[3][1], ap3, b.y);
    }

    #pragma unroll
    for (int i = 0; i < 4; i++) {
        const int q    = tq0 + i;
        const float xn = sqxn[q];
        const float w0 = sqw[q][0], w1 = sqw[q][1], w2 = sqw[q][2];
        const float beta = 1.0f - xn;

        float ev[4], hv[4], sv[4];
        unpack2(ev[0], ev[1], ae[i][0]);  unpack2(ev[2], ev[3], ae[i][1]);
        unpack2(hv[0], hv[1], ah[i][0]);  unpack2(hv[2], hv[3], ah[i][1]);
        unpack2(sv[0], sv[1], as2[i][0]); unpack2(sv[2], sv[3], as2[i][1]);

        float rv[4];
        #pragma unroll
        for (int j = 0; j < 4; j++) {
            const float yn = scyn[tc0 + j];
            float de = 2.0f - 2.0f * ev[j];
            float dots = fminf(fmaxf(sv[j], -1.0f + 1e-7f), 1.0f - 1e-7f);
            float acs  = acosf(dots);
            float ds   = acs * acs;
            float dt    = hv[j];
            float alpha = 1.0f - 2.0f * dt + yn;
            float nsq   = alpha*alpha*xn - 2.0f*alpha*beta*dt + beta*beta*yn;
            float den   = fmaxf(1.0f - 2.0f*dt + xn*yn, 1e-15f);
            float t     = __fdividef(sqrtf(fmaxf(nsq, 0.0f)), den);
            t = fminf(fmaxf(t, 0.0f), 1.0f - 1e-7f);
            float dd = __logf(__fdividef(1.0f + t, 1.0f - t));
            float dh = dd * dd;
            rv[j] = -(w0 * de + w1 * dh + w2 * ds);
        }
        float4 res = {rv[0], rv[1], rv[2], rv[3]};
        *(float4*)(out + (size_t)(q0blk + q) * NC + c0blk + tc0) = res;
    }
}

// ---------------------------------------------------------------------------
extern "C" void kernel_launch(void* const* d_in, const int* in_sizes, int n_in,
                              void* d_out, int out_size)
{
    const float* xq  = (const float*)d_in[0];
    const float* xc  = (const float*)d_in[1];
    const float* We  = (const float*)d_in[2];
    const float* be  = (const float*)d_in[3];
    const float* Wh  = (const float*)d_in[4];
    const float* bh  = (const float*)d_in[5];
    const float* Ws  = (const float*)d_in[6];
    const float* bs  = (const float*)d_in[7];
    const float* sh  = (const float*)d_in[8];
    const float* W1  = (const float*)d_in[9];
    const float* b1  = (const float*)d_in[10];
    const float* W2  = (const float*)d_in[11];
    const float* b2  = (const float*)d_in[12];
    float* out = (float*)d_out;

    mlp_kernel<<<NQ, 256>>>(xq, W1, b1, W2, b2);
    proj_kernel<<<NCB128 + NQB128, 256>>>(xc, xq, We, be, Wh, bh, Ws, bs, sh);
    pairwise_kernel<<<dim3(NC / 64, NQ / 64), 256>>>(out);
}